// round 5
// baseline (speedup 1.0000x reference)
#include <cuda_runtime.h>
#include <cstdint>

#define M_B 128
#define N_F 1024
#define K_F 1024
#define KSPLIT 8
#define BN 32
#define KT 32
#define KCHUNK (K_F / KSPLIT)      /* 128 */
#define NITER (KCHUNK / KT)        /* 4 */
#define NB_GROUPS (N_F / BN)       /* 32 */
#define GRID (NB_GROUPS * KSPLIT)  /* 256 — 2 CTAs/SM, all resident */

// Scratch (device globals: no allocation allowed in kernel_launch)
__device__ float g_partial[KSPLIT * M_B * N_F];       // 4 MB split-K partials
__device__ float2 g_upart[KSPLIT][M_B];               // per-chunk u partials
__device__ unsigned int g_done[NB_GROUPS * 32];       // per-nb monotonic counters (128B apart)

// ---------------------------------------------------------------------------
__device__ __forceinline__ void cp_async16(void* smem, const void* gmem) {
    uint32_t s = (uint32_t)__cvta_generic_to_shared(smem);
    asm volatile("cp.async.cg.shared.global [%0], [%1], 16;\n" :: "r"(s), "l"(gmem));
}
__device__ __forceinline__ void cp_commit() {
    asm volatile("cp.async.commit_group;\n");
}
template <int N>
__device__ __forceinline__ void cp_wait() {
    asm volatile("cp.async.wait_group %0;\n" :: "n"(N));
}
__device__ __forceinline__ uint32_t f2tf32(float x) {
    uint32_t r;
    asm("cvt.rna.tf32.f32 %0, %1;" : "=r"(r) : "f"(x));
    return r;
}

// ---------------------------------------------------------------------------
// Persistent dataflow kernel, 256 CTAs:
//  CTA (nb, ks):  split-K tf32 GEMM tile 128 x 32 for K-chunk ks
//                 (nb==0 CTAs also compute u_part[ks] = input . A over chunk)
//                 fence; atomicAdd(g_done[nb])
//  CTA (nb, 0):   poll g_done[nb] and g_done[0] to target (monotonic, replay-
//                 safe), then reduce 8 partials + bias + rank-2 epilogue for
//                 columns [nb*32, nb*32+32) of all 128 rows.
// ---------------------------------------------------------------------------
__global__ __launch_bounds__(256, 2) void fused_kernel(
        const float* __restrict__ input,
        const float* __restrict__ codes,
        const float* __restrict__ weight,
        const float* __restrict__ A,
        const float* __restrict__ Bm,
        const float* __restrict__ bias,
        const float* __restrict__ bctx,
        float* __restrict__ out) {
    __shared__ float sA[2][128][KT + 4];   // stride 36, conflict-free frag loads
    __shared__ float sB[2][KT][BN + 8];    // stride 40, conflict-free frag loads

    int tid = threadIdx.x;
    int bid = blockIdx.x;
    int nb_idx = bid & (NB_GROUPS - 1);
    int ks = bid >> 5;
    int nb = nb_idx * BN;
    int k_base = ks * KCHUNK;

    // ======================= Phase 1: GEMM =======================
    {
        int wid = tid >> 5, lane = tid & 31;
        int wm = wid & 3, wn = wid >> 2;
        int m_base = wm * 32, n_base = wn * 16;
        int g = lane >> 2, q = lane & 3;

        int a_row = tid >> 3, a_c4 = (tid & 7) * 4;
        int b_row = tid >> 3, b_c4 = (tid & 7) * 4;

        float acc[2][2][4];
        #pragma unroll
        for (int mi = 0; mi < 2; mi++)
            #pragma unroll
            for (int ni = 0; ni < 2; ni++)
                #pragma unroll
                for (int r = 0; r < 4; r++) acc[mi][ni][r] = 0.f;

        // prefetch stage 0 (async — u_part LDGs below overlap with it)
        {
            int k0 = k_base;
            #pragma unroll
            for (int t = 0; t < 4; t++) {
                int row = a_row + t * 32;
                cp_async16(&sA[0][row][a_c4], input + row * K_F + k0 + a_c4);
            }
            cp_async16(&sB[0][b_row][b_c4], weight + (k0 + b_row) * N_F + nb + b_c4);
            cp_commit();
        }

        // ---- u_part for this K-chunk (nb==0 CTAs only): u = input . A ----
        if (nb_idx == 0) {
            int b = tid >> 1;
            int k0 = k_base + (tid & 1) * 64;
            float p0 = 0.f, p1 = 0.f;
            const float2* A2 = reinterpret_cast<const float2*>(A);
            #pragma unroll
            for (int i = 0; i < 16; i++) {
                float4 x = *reinterpret_cast<const float4*>(input + b * K_F + k0 + i * 4);
                float2 a0 = A2[k0 + i * 4 + 0];
                float2 a1 = A2[k0 + i * 4 + 1];
                float2 a2 = A2[k0 + i * 4 + 2];
                float2 a3 = A2[k0 + i * 4 + 3];
                p0 += x.x * a0.x + x.y * a1.x + x.z * a2.x + x.w * a3.x;
                p1 += x.x * a0.y + x.y * a1.y + x.z * a2.y + x.w * a3.y;
            }
            p0 += __shfl_xor_sync(0xFFFFFFFFu, p0, 1);
            p1 += __shfl_xor_sync(0xFFFFFFFFu, p1, 1);
            if ((tid & 1) == 0) g_upart[ks][b] = make_float2(p0, p1);
        }

        for (int s = 0; s < NITER; s++) {
            int buf = s & 1;
            if (s + 1 < NITER) {
                int k0 = k_base + (s + 1) * KT;
                int nbuf = (s + 1) & 1;
                #pragma unroll
                for (int t = 0; t < 4; t++) {
                    int row = a_row + t * 32;
                    cp_async16(&sA[nbuf][row][a_c4], input + row * K_F + k0 + a_c4);
                }
                cp_async16(&sB[nbuf][b_row][b_c4],
                           weight + (k0 + b_row) * N_F + nb + b_c4);
                cp_commit();
                cp_wait<1>();
            } else {
                cp_wait<0>();
            }
            __syncthreads();

            #pragma unroll
            for (int kk = 0; kk < KT; kk += 8) {
                uint32_t afr[2][4], bfr[2][2];
                #pragma unroll
                for (int mi = 0; mi < 2; mi++) {
                    int r0 = m_base + mi * 16 + g;
                    afr[mi][0] = f2tf32(sA[buf][r0    ][kk + q    ]);
                    afr[mi][1] = f2tf32(sA[buf][r0 + 8][kk + q    ]);
                    afr[mi][2] = f2tf32(sA[buf][r0    ][kk + q + 4]);
                    afr[mi][3] = f2tf32(sA[buf][r0 + 8][kk + q + 4]);
                }
                #pragma unroll
                for (int ni = 0; ni < 2; ni++) {
                    int c0 = n_base + ni * 8 + g;
                    bfr[ni][0] = f2tf32(sB[buf][kk + q    ][c0]);
                    bfr[ni][1] = f2tf32(sB[buf][kk + q + 4][c0]);
                }
                #pragma unroll
                for (int mi = 0; mi < 2; mi++)
                    #pragma unroll
                    for (int ni = 0; ni < 2; ni++) {
                        asm volatile(
                            "mma.sync.aligned.m16n8k8.row.col.f32.tf32.tf32.f32 "
                            "{%0,%1,%2,%3}, {%4,%5,%6,%7}, {%8,%9}, {%0,%1,%2,%3};\n"
                            : "+f"(acc[mi][ni][0]), "+f"(acc[mi][ni][1]),
                              "+f"(acc[mi][ni][2]), "+f"(acc[mi][ni][3])
                            : "r"(afr[mi][0]), "r"(afr[mi][1]),
                              "r"(afr[mi][2]), "r"(afr[mi][3]),
                              "r"(bfr[ni][0]), "r"(bfr[ni][1]));
                    }
            }
            __syncthreads();
        }

        // write split-K partials
        float* part = g_partial + ks * (M_B * N_F);
        #pragma unroll
        for (int mi = 0; mi < 2; mi++)
            #pragma unroll
            for (int ni = 0; ni < 2; ni++) {
                int row = m_base + mi * 16 + g;
                int col = nb + n_base + ni * 8 + q * 2;
                part[row * N_F + col]           = acc[mi][ni][0];
                part[row * N_F + col + 1]       = acc[mi][ni][1];
                part[(row + 8) * N_F + col]     = acc[mi][ni][2];
                part[(row + 8) * N_F + col + 1] = acc[mi][ni][3];
            }
    }

    // ================== arrival (per-nb counter, monotonic) ==================
    __threadfence();
    __syncthreads();
    __shared__ unsigned int s_ticket;
    if (tid == 0) {
        unsigned int t = atomicAdd(&g_done[nb_idx * 32], 1u);
        if (ks == 0) s_ticket = t;
    }

    if (ks != 0) return;   // producers done; reducer continues

    // =================== reducer: wait for my 8 producers + prep ============
    __syncthreads();
    if (tid == 0) {
        unsigned int target = (s_ticket / KSPLIT + 1u) * KSPLIT;
        volatile unsigned int* own = &g_done[nb_idx * 32];
        while (*own < target) { }
        volatile unsigned int* pre = &g_done[0];
        while (*pre < target) { }       // u_part producers (nb==0 group)
    }
    __syncthreads();
    __threadfence();

    // v,d for all 128 rows -> smem (reuse sA storage)
    float4* s_v = reinterpret_cast<float4*>(&sA[0][0][0]);
    if (tid < M_B) {
        float u0 = 0.f, u1 = 0.f;
        #pragma unroll
        for (int k = 0; k < KSPLIT; k++) {
            float2 up = g_upart[k][tid];
            u0 += up.x; u1 += up.y;
        }
        float c00 = codes[tid * 4 + 0], c01 = codes[tid * 4 + 1];
        float c10 = codes[tid * 4 + 2], c11 = codes[tid * 4 + 3];
        s_v[tid] = make_float4(u0 * c00 + u1 * c10,   // v0
                               u0 * c01 + u1 * c11,   // v1
                               c00, c11);             // d0, d1
    }
    __syncthreads();

    // ============ reduce 8 partials + epilogue for cols [nb, nb+32) ==========
    {
        int c4 = (tid & 7) * 4;
        int j4 = nb + c4;
        float4 bi = *reinterpret_cast<const float4*>(bias + j4);
        float4 B0 = *reinterpret_cast<const float4*>(Bm + j4);
        float4 B1 = *reinterpret_cast<const float4*>(Bm + N_F + j4);
        float4 e0 = *reinterpret_cast<const float4*>(bctx + j4);
        float4 e1 = *reinterpret_cast<const float4*>(bctx + N_F + j4);

        #pragma unroll
        for (int p = 0; p < 4; p++) {
            int b = (tid >> 3) + p * 32;
            float4 s = *reinterpret_cast<const float4*>(&g_partial[b * N_F + j4]);
            #pragma unroll
            for (int k = 1; k < KSPLIT; k++) {
                float4 q2 = *reinterpret_cast<const float4*>(
                    &g_partial[k * (M_B * N_F) + b * N_F + j4]);
                s.x += q2.x; s.y += q2.y; s.z += q2.z; s.w += q2.w;
            }
            float4 vd = s_v[b];
            float4 o;
            o.x = s.x + bi.x + vd.x * B0.x + vd.y * B1.x + vd.z * e0.x + vd.w * e1.x;
            o.y = s.y + bi.y + vd.x * B0.y + vd.y * B1.y + vd.z * e0.y + vd.w * e1.y;
            o.z = s.z + bi.z + vd.x * B0.z + vd.y * B1.z + vd.z * e0.z + vd.w * e1.z;
            o.w = s.w + bi.w + vd.x * B0.w + vd.y * B1.w + vd.z * e0.w + vd.w * e1.w;
            *reinterpret_cast<float4*>(out + b * N_F + j4) = o;
        }
    }
}

extern "C" void kernel_launch(void* const* d_in, const int* in_sizes, int n_in,
                              void* d_out, int out_size) {
    const float* input  = (const float*)d_in[0];
    const float* codes  = (const float*)d_in[1];
    const float* weight = (const float*)d_in[2];
    const float* A      = (const float*)d_in[3];
    const float* Bm     = (const float*)d_in[4];
    const float* bias   = (const float*)d_in[5];
    const float* bctx   = (const float*)d_in[6];
    float* out = (float*)d_out;

    fused_kernel<<<GRID, 256>>>(input, codes, weight, A, Bm, bias, bctx, out);
}

// round 6
// speedup vs baseline: 2.1500x; 2.1500x over previous
#include <cuda_runtime.h>
#include <cstdint>

#define M_B 128
#define N_F 1024
#define K_F 1024
#define KSPLIT 8
#define BN 64
#define KT 32
#define KCHUNK (K_F / KSPLIT)      /* 128 */
#define NITER (KCHUNK / KT)        /* 4 */
#define GRID 128                   /* 16 nb-groups x 8 ks — single wave, barrier-safe */

// Scratch (device globals: no allocation allowed in kernel_launch)
__device__ float g_partial[KSPLIT * M_B * N_F];   // 4 MB split-K partials
__device__ unsigned int g_cnt = 0;                 // monotonic ticket barrier

// ---------------------------------------------------------------------------
__device__ __forceinline__ void cp_async16(void* smem, const void* gmem) {
    uint32_t s = (uint32_t)__cvta_generic_to_shared(smem);
    asm volatile("cp.async.cg.shared.global [%0], [%1], 16;\n" :: "r"(s), "l"(gmem));
}
__device__ __forceinline__ void cp_commit() {
    asm volatile("cp.async.commit_group;\n");
}
template <int N>
__device__ __forceinline__ void cp_wait() {
    asm volatile("cp.async.wait_group %0;\n" :: "n"(N));
}

// ---------------------------------------------------------------------------
// Persistent kernel, 128 CTAs (single wave):
//   Phase 1: split-K tf32 GEMM, block tile 128(M) x 64(N), K-chunk 128.
//            8 warps as 4m x 2n, warp tile 32x32 (mi=2, ni=4).
//            RAW fp32 bits fed to tf32 MMA (no cvt — HW truncation).
//            + prep u = input_b . A -> v,d (pre-barrier, CTA b)
//   grid ticket barrier
//   Phase 2: CTA b -> reduce 8 partials + bias + rank-2 epilogue for row b.
// ---------------------------------------------------------------------------
__global__ __launch_bounds__(256) void fused_kernel(
        const float* __restrict__ input,
        const float* __restrict__ codes,
        const float* __restrict__ weight,
        const float* __restrict__ A,
        const float* __restrict__ Bm,
        const float* __restrict__ bias,
        const float* __restrict__ bctx,
        float* __restrict__ out) {
    __shared__ float sA[2][128][KT + 4];   // stride 36: conflict-free frag loads
    __shared__ float sB[2][KT][BN + 8];    // stride 72: conflict-free frag loads
    __shared__ float s_red[8][2];

    int tid = threadIdx.x;
    int bid = blockIdx.x;

    // ======================= Phase 1: GEMM =======================
    {
        int nb = (bid & 15) * BN;          // 16 nb-groups
        int ks = bid >> 4;                 // 8 ks
        int k_base = ks * KCHUNK;

        int wid = tid >> 5, lane = tid & 31;
        int wm = wid & 3, wn = wid >> 2;
        int m_base = wm * 32, n_base = wn * 32;
        int g = lane >> 2, q = lane & 3;

        int a_row = tid >> 3, a_c4 = (tid & 7) * 4;     // 4 iters of 32 rows
        int b_row = tid >> 4, b_c4 = (tid & 15) * 4;    // 2 iters of 16 rows

        float acc[2][4][4];
        #pragma unroll
        for (int mi = 0; mi < 2; mi++)
            #pragma unroll
            for (int ni = 0; ni < 4; ni++)
                #pragma unroll
                for (int r = 0; r < 4; r++) acc[mi][ni][r] = 0.f;

        // prefetch stage 0
        {
            int k0 = k_base;
            #pragma unroll
            for (int t = 0; t < 4; t++) {
                int row = a_row + t * 32;
                cp_async16(&sA[0][row][a_c4], input + row * K_F + k0 + a_c4);
            }
            #pragma unroll
            for (int t = 0; t < 2; t++) {
                int row = b_row + t * 16;
                cp_async16(&sB[0][row][b_c4], weight + (k0 + row) * N_F + nb + b_c4);
            }
            cp_commit();
        }

        for (int s = 0; s < NITER; s++) {
            int buf = s & 1;
            if (s + 1 < NITER) {
                int k0 = k_base + (s + 1) * KT;
                int nbuf = (s + 1) & 1;
                #pragma unroll
                for (int t = 0; t < 4; t++) {
                    int row = a_row + t * 32;
                    cp_async16(&sA[nbuf][row][a_c4], input + row * K_F + k0 + a_c4);
                }
                #pragma unroll
                for (int t = 0; t < 2; t++) {
                    int row = b_row + t * 16;
                    cp_async16(&sB[nbuf][row][b_c4],
                               weight + (k0 + row) * N_F + nb + b_c4);
                }
                cp_commit();
                cp_wait<1>();
            } else {
                cp_wait<0>();
            }
            __syncthreads();

            #pragma unroll
            for (int kk = 0; kk < KT; kk += 8) {
                uint32_t afr[2][4], bfr[4][2];
                // raw fp32 bits — tf32 MMA truncates mantissa in HW
                #pragma unroll
                for (int mi = 0; mi < 2; mi++) {
                    int r0 = m_base + mi * 16 + g;
                    afr[mi][0] = __float_as_uint(sA[buf][r0    ][kk + q    ]);
                    afr[mi][1] = __float_as_uint(sA[buf][r0 + 8][kk + q    ]);
                    afr[mi][2] = __float_as_uint(sA[buf][r0    ][kk + q + 4]);
                    afr[mi][3] = __float_as_uint(sA[buf][r0 + 8][kk + q + 4]);
                }
                #pragma unroll
                for (int ni = 0; ni < 4; ni++) {
                    int c0 = n_base + ni * 8 + g;
                    bfr[ni][0] = __float_as_uint(sB[buf][kk + q    ][c0]);
                    bfr[ni][1] = __float_as_uint(sB[buf][kk + q + 4][c0]);
                }
                #pragma unroll
                for (int mi = 0; mi < 2; mi++)
                    #pragma unroll
                    for (int ni = 0; ni < 4; ni++) {
                        asm volatile(
                            "mma.sync.aligned.m16n8k8.row.col.f32.tf32.tf32.f32 "
                            "{%0,%1,%2,%3}, {%4,%5,%6,%7}, {%8,%9}, {%0,%1,%2,%3};\n"
                            : "+f"(acc[mi][ni][0]), "+f"(acc[mi][ni][1]),
                              "+f"(acc[mi][ni][2]), "+f"(acc[mi][ni][3])
                            : "r"(afr[mi][0]), "r"(afr[mi][1]),
                              "r"(afr[mi][2]), "r"(afr[mi][3]),
                              "r"(bfr[ni][0]), "r"(bfr[ni][1]));
                    }
            }
            __syncthreads();
        }

        // write split-K partials
        float* part = g_partial + ks * (M_B * N_F);
        #pragma unroll
        for (int mi = 0; mi < 2; mi++)
            #pragma unroll
            for (int ni = 0; ni < 4; ni++) {
                int row = m_base + mi * 16 + g;
                int col = nb + n_base + ni * 8 + q * 2;
                part[row * N_F + col]           = acc[mi][ni][0];
                part[row * N_F + col + 1]       = acc[mi][ni][1];
                part[(row + 8) * N_F + col]     = acc[mi][ni][2];
                part[(row + 8) * N_F + col + 1] = acc[mi][ni][3];
            }
    }

    // ---- prep (pre-barrier, independent of partials): CTA b = bid ----
    float v0, v1, d0, d1;
    {
        int b = bid;
        float4 x = *reinterpret_cast<const float4*>(input + b * K_F + tid * 4);
        const float2* A2 = reinterpret_cast<const float2*>(A);
        float2 a0 = A2[tid * 4 + 0];
        float2 a1 = A2[tid * 4 + 1];
        float2 a2 = A2[tid * 4 + 2];
        float2 a3 = A2[tid * 4 + 3];
        float p0 = x.x * a0.x + x.y * a1.x + x.z * a2.x + x.w * a3.x;
        float p1 = x.x * a0.y + x.y * a1.y + x.z * a2.y + x.w * a3.y;
        #pragma unroll
        for (int off = 16; off > 0; off >>= 1) {
            p0 += __shfl_xor_sync(0xFFFFFFFFu, p0, off);
            p1 += __shfl_xor_sync(0xFFFFFFFFu, p1, off);
        }
        int w = tid >> 5, lane = tid & 31;
        if (lane == 0) { s_red[w][0] = p0; s_red[w][1] = p1; }
        __syncthreads();
        float u0 = 0.f, u1 = 0.f;
        #pragma unroll
        for (int i = 0; i < 8; i++) { u0 += s_red[i][0]; u1 += s_red[i][1]; }
        float c00 = codes[b * 4 + 0], c01 = codes[b * 4 + 1];
        float c10 = codes[b * 4 + 2], c11 = codes[b * 4 + 3];
        v0 = u0 * c00 + u1 * c10;
        v1 = u0 * c01 + u1 * c11;
        d0 = c00;
        d1 = c11;
    }

    // ================== grid-wide ticket barrier ==================
    __threadfence();
    __syncthreads();
    if (tid == 0) {
        unsigned int ticket = atomicAdd(&g_cnt, 1u);
        unsigned int target = (ticket / GRID + 1u) * GRID;
        while (*((volatile unsigned int*)&g_cnt) < target) { }
    }
    __syncthreads();
    __threadfence();

    // ============ Phase 2: split-K reduce + epilogue (CTA b = bid) ============
    {
        int b = bid;
        int j4 = tid * 4;
        float4 s = *reinterpret_cast<const float4*>(&g_partial[b * N_F + j4]);
        #pragma unroll
        for (int ks = 1; ks < KSPLIT; ks++) {
            float4 p = *reinterpret_cast<const float4*>(
                &g_partial[ks * (M_B * N_F) + b * N_F + j4]);
            s.x += p.x; s.y += p.y; s.z += p.z; s.w += p.w;
        }
        float4 bi = *reinterpret_cast<const float4*>(bias + j4);
        float4 B0 = *reinterpret_cast<const float4*>(Bm + j4);
        float4 B1 = *reinterpret_cast<const float4*>(Bm + N_F + j4);
        float4 e0 = *reinterpret_cast<const float4*>(bctx + j4);
        float4 e1 = *reinterpret_cast<const float4*>(bctx + N_F + j4);

        float4 o;
        o.x = s.x + bi.x + v0 * B0.x + v1 * B1.x + d0 * e0.x + d1 * e1.x;
        o.y = s.y + bi.y + v0 * B0.y + v1 * B1.y + d0 * e0.y + d1 * e1.y;
        o.z = s.z + bi.z + v0 * B0.z + v1 * B1.z + d0 * e0.z + d1 * e1.z;
        o.w = s.w + bi.w + v0 * B0.w + v1 * B1.w + d0 * e0.w + d1 * e1.w;
        *reinterpret_cast<float4*>(out + b * N_F + j4) = o;
    }
}

extern "C" void kernel_launch(void* const* d_in, const int* in_sizes, int n_in,
                              void* d_out, int out_size) {
    const float* input  = (const float*)d_in[0];
    const float* codes  = (const float*)d_in[1];
    const float* weight = (const float*)d_in[2];
    const float* A      = (const float*)d_in[3];
    const float* Bm     = (const float*)d_in[4];
    const float* bias   = (const float*)d_in[5];
    const float* bctx   = (const float*)d_in[6];
    float* out = (float*)d_out;

    fused_kernel<<<GRID, 256>>>(input, codes, weight, A, Bm, bias, bctx, out);
}